// round 4
// baseline (speedup 1.0000x reference)
#include <cuda_runtime.h>
#include <math.h>
#include <stdint.h>

#define OBS   128
#define PROJ  64
#define HID   256
#define LAT   24
#define BB    1024
#define TT    256
#define G3    768

// ---- device scratch --------------------------------------------------------
__device__ float  g_gx [(size_t)BB * TT * G3];   // input-side gates [B*T,768]
__device__ float  g_seq[(size_t)BB * TT * HID];  // h_new per step   [B*T,256]
__device__ float4 g_Wt4[(HID / 4) * G3];         // W_hh repacked [k4][col] float4

// ---- helpers ---------------------------------------------------------------
__device__ __forceinline__ void fma2(float2& d, float2 a, float2 b) {
    unsigned long long& dd = reinterpret_cast<unsigned long long&>(d);
    asm("fma.rn.f32x2 %0, %1, %2, %0;"
        : "+l"(dd)
        : "l"(reinterpret_cast<const unsigned long long&>(a)),
          "l"(reinterpret_cast<const unsigned long long&>(b)));
}
__device__ __forceinline__ float tanha(float x) {
    float y; asm("tanh.approx.f32 %0, %1;" : "=f"(y) : "f"(x)); return y;
}
__device__ __forceinline__ float siga(float x) {       // sigmoid via MUFU.TANH
    return fmaf(0.5f, tanha(0.5f * x), 0.5f);
}

// ---- W_hh repack: g_Wt4[k4*768+col] = {W[4k4][col],...,W[4k4+3][col]} ------
__global__ void tr_kernel(const float* __restrict__ W) {
    int idx = blockIdx.x * 256 + threadIdx.x;
    if (idx >= (HID / 4) * G3) return;
    int k4 = idx / G3, col = idx - k4 * G3;
    float4 v;
    v.x = W[(size_t)(4 * k4 + 0) * G3 + col];
    v.y = W[(size_t)(4 * k4 + 1) * G3 + col];
    v.z = W[(size_t)(4 * k4 + 2) * G3 + col];
    v.w = W[(size_t)(4 * k4 + 3) * G3 + col];
    g_Wt4[idx] = v;
}

// ---- pre: gx = (obs@W_in + b_in)@W_ih + b_ih, FFMA2-packed over row pairs --
__global__ __launch_bounds__(256) void pre_kernel(
    const float* __restrict__ obs, const float* __restrict__ W_in,
    const float* __restrict__ b_in, const float* __restrict__ W_ih,
    const float* __restrict__ b_ih)
{
    __shared__ float s_obsT[OBS][34];
    __shared__ float s_x2[PROJ][34];

    const int tid = threadIdx.x;
    const size_t row0 = (size_t)blockIdx.x * 32;

    for (int i = tid; i < 32 * OBS; i += 256) {
        int r = i >> 7, k = i & 127;
        s_obsT[k][r] = obs[(row0 + r) * OBS + k];
    }
    __syncthreads();

    {
        const int p = tid & 63, rh = tid >> 6;
        const float bi = b_in[p];
        float2 acc[4];
        #pragma unroll
        for (int pr = 0; pr < 4; pr++) acc[pr] = make_float2(bi, bi);
        #pragma unroll 4
        for (int k = 0; k < OBS; k++) {
            float w = W_in[k * PROJ + p];
            float2 w2 = make_float2(w, w);
            #pragma unroll
            for (int pr = 0; pr < 4; pr++)
                fma2(acc[pr], w2, *(const float2*)&s_obsT[k][8 * rh + 2 * pr]);
        }
        #pragma unroll
        for (int pr = 0; pr < 4; pr++) {
            s_x2[p][8 * rh + 2 * pr]     = acc[pr].x;
            s_x2[p][8 * rh + 2 * pr + 1] = acc[pr].y;
        }
    }
    __syncthreads();

    const int j = tid;
    const float bh0 = b_ih[j], bh1 = b_ih[j + 256], bh2 = b_ih[j + 512];
    for (int rt = 0; rt < 2; rt++) {
        float2 a0[8], a1[8], a2[8];
        #pragma unroll
        for (int pr = 0; pr < 8; pr++) {
            a0[pr] = make_float2(bh0, bh0);
            a1[pr] = make_float2(bh1, bh1);
            a2[pr] = make_float2(bh2, bh2);
        }
        #pragma unroll 2
        for (int p = 0; p < PROJ; p++) {
            float w0 = W_ih[p * G3 + j];
            float w1 = W_ih[p * G3 + j + 256];
            float w2 = W_ih[p * G3 + j + 512];
            float2 w02 = make_float2(w0, w0);
            float2 w12 = make_float2(w1, w1);
            float2 w22 = make_float2(w2, w2);
            #pragma unroll
            for (int pr = 0; pr < 8; pr++) {
                float2 xv = *(const float2*)&s_x2[p][16 * rt + 2 * pr];
                fma2(a0[pr], w02, xv);
                fma2(a1[pr], w12, xv);
                fma2(a2[pr], w22, xv);
            }
        }
        #pragma unroll
        for (int pr = 0; pr < 8; pr++) {
            size_t r = row0 + rt * 16 + 2 * pr;
            g_gx[r * G3 + j]             = a0[pr].x;
            g_gx[(r + 1) * G3 + j]       = a0[pr].y;
            g_gx[r * G3 + j + 256]       = a1[pr].x;
            g_gx[(r + 1) * G3 + j + 256] = a1[pr].y;
            g_gx[r * G3 + j + 512]       = a2[pr].x;
            g_gx[(r + 1) * G3 + j + 512] = a2[pr].y;
        }
    }
}

// ---- rec: cluster-2 persistent GRU scan, 512 thr/CTA (16 warps) ------------
// 64 clusters x 2 CTAs. Cluster c: batch rows 16c..16c+15.
// CTA rank q: hidden units q*128..q*128+127.
// Thread: uu = tid&127 (unit), rg = tid>>7 (0..3) -> rows 4rg..4rg+3
// (pairs p0=2rg, p0+1). 8-k weight blocks, two 6-float4 buffers, depth-1
// prefetch. h in SMEM pair-packed s_hp[buf][k][pair].

#define LDW8(dst, bb)                                           \
    {                                                           \
        _Pragma("unroll")                                       \
        for (int u = 0; u < 2; u++) {                           \
            size_t kb = (size_t)(2 * (bb) + u) * G3;            \
            dst[3 * u + 0] = g_Wt4[kb + gu];                    \
            dst[3 * u + 1] = g_Wt4[kb + 256 + gu];              \
            dst[3 * u + 2] = g_Wt4[kb + 512 + gu];              \
        }                                                       \
    }

#define COMP8(buf, bb)                                                        \
    {                                                                         \
        _Pragma("unroll")                                                     \
        for (int u = 0; u < 2; u++) {                                         \
            float4 wr = buf[3 * u], wz = buf[3 * u + 1], wn = buf[3 * u + 2]; \
            float wra[4] = {wr.x, wr.y, wr.z, wr.w};                          \
            float wza[4] = {wz.x, wz.y, wz.z, wz.w};                          \
            float wna[4] = {wn.x, wn.y, wn.z, wn.w};                          \
            _Pragma("unroll")                                                 \
            for (int kk = 0; kk < 4; kk++) {                                  \
                int k = 8 * (bb) + 4 * u + kk;                                \
                float4 hA = *(const float4*)&s_hp[rb][k][p0];                 \
                float2 h0 = make_float2(hA.x, hA.y);                          \
                float2 h1 = make_float2(hA.z, hA.w);                          \
                float2 w2;                                                    \
                w2 = make_float2(wra[kk], wra[kk]);                           \
                fma2(ar[0], w2, h0); fma2(ar[1], w2, h1);                     \
                w2 = make_float2(wza[kk], wza[kk]);                           \
                fma2(az[0], w2, h0); fma2(az[1], w2, h1);                     \
                w2 = make_float2(wna[kk], wna[kk]);                           \
                fma2(an[0], w2, h0); fma2(an[1], w2, h1);                     \
            }                                                                 \
        }                                                                     \
    }

__global__ __launch_bounds__(512) __cluster_dims__(2, 1, 1)
void rec_kernel(const int* __restrict__ is_init, const float* __restrict__ hx,
                const float* __restrict__ b_hh, float* __restrict__ h_final)
{
    __shared__ float2 s_hp[2][HID][8];          // 32 KB
    __shared__ unsigned char s_rst[16][TT];     //  4 KB

    const int tid = threadIdx.x;
    const int q   = blockIdx.x & 1;
    const int b0  = (blockIdx.x >> 1) * 16;
    const int uu  = tid & 127;
    const int rg  = tid >> 7;                   // 0..3
    const int gu  = q * 128 + uu;
    const int p0  = rg * 2;                     // 2 pairs
    const int r0  = rg * 4;                     // 4 rows

    for (int i = tid; i < 16 * TT; i += 512) {
        int r = i >> 8, t = i & 255;
        s_rst[r][t] = (unsigned char)(is_init[(b0 + r) * TT + t] != 0);
    }
    for (int i = tid; i < HID * 8; i += 512) {
        int k = i >> 3, p = i & 7;
        float h0 = (is_init[(b0 + 2 * p) * TT] != 0)     ? 0.f : hx[(b0 + 2 * p) * HID + k];
        float h1 = (is_init[(b0 + 2 * p + 1) * TT] != 0) ? 0.f : hx[(b0 + 2 * p + 1) * HID + k];
        s_hp[0][k][p] = make_float2(h0, h1);
    }
    __syncthreads();

    const float bhr = b_hh[gu], bhz = b_hh[256 + gu], bhn = b_hh[512 + gu];

    uint32_t my_base;
    asm("{ .reg .u64 t0; cvta.to.shared.u64 t0, %1; cvt.u32.u64 %0, t0; }"
        : "=r"(my_base) : "l"(&s_hp[0][0][0]));
    uint32_t peer_base;
    asm("mapa.shared::cluster.u32 %0, %1, %2;"
        : "=r"(peer_base) : "r"(my_base), "r"(q ^ 1));

    for (int t = 0; t < TT; t++) {
        const int rb = t & 1, wb = rb ^ 1;

        // prefetch input-side gates for this thread's 4 rows
        float gxr[4], gxz[4], gxn[4];
        #pragma unroll
        for (int r = 0; r < 4; r++) {
            const float* g = g_gx + ((size_t)(b0 + r0 + r) * TT + t) * G3;
            gxr[r] = g[gu]; gxz[r] = g[256 + gu]; gxn[r] = g[512 + gu];
        }
        float hprev[4];
        #pragma unroll
        for (int p = 0; p < 2; p++) {
            float2 v = s_hp[rb][gu][p0 + p];
            hprev[2 * p] = v.x; hprev[2 * p + 1] = v.y;
        }

        // GEMV: 32 blocks of 8 k, two buffers, depth-1 prefetch
        float2 ar[2], az[2], an[2];
        ar[0] = ar[1] = az[0] = az[1] = an[0] = an[1] = make_float2(0.f, 0.f);
        float4 wA[6], wB[6];
        LDW8(wA, 0);
        LDW8(wB, 1);
        #pragma unroll 1
        for (int b = 0; b < 30; b += 2) {
            COMP8(wA, b);
            LDW8(wA, b + 2);
            COMP8(wB, b + 1);
            LDW8(wB, b + 3);
        }
        COMP8(wA, 30);
        COMP8(wB, 31);

        // gates (MUFU.TANH)
        float hnew[4];
        #pragma unroll
        for (int p = 0; p < 2; p++) {
            float gr[2] = {ar[p].x, ar[p].y};
            float gz[2] = {az[p].x, az[p].y};
            float gn[2] = {an[p].x, an[p].y};
            #pragma unroll
            for (int e = 0; e < 2; e++) {
                int r = 2 * p + e;
                float rr = siga(gxr[r] + gr[e] + bhr);
                float zz = siga(gxz[r] + gz[e] + bhz);
                float nn = tanha(gxn[r] + rr * (gn[e] + bhn));
                hnew[r] = nn + zz * (hprev[r] - nn);
            }
        }

        if (t == TT - 1) {
            #pragma unroll
            for (int r = 0; r < 4; r++) {
                g_seq[((size_t)(b0 + r0 + r) * TT + t) * HID + gu] = hnew[r];
                h_final[(b0 + r0 + r) * HID + gu] = hnew[r];
            }
            break;
        }

        // write (t+1)-masked h pairs locally + to peer; overlap g_seq stores
        // with the cluster barrier.
        #pragma unroll
        for (int p = 0; p < 2; p++) {
            float2 v;
            v.x = s_rst[r0 + 2 * p][t + 1]     ? 0.f : hnew[2 * p];
            v.y = s_rst[r0 + 2 * p + 1][t + 1] ? 0.f : hnew[2 * p + 1];
            s_hp[wb][gu][p0 + p] = v;
            uint32_t off = (uint32_t)(((wb * HID + gu) * 8 + p0 + p) * sizeof(float2));
            asm volatile("st.shared::cluster.b64 [%0], %1;"
                         :: "r"(peer_base + off),
                            "l"(*(const unsigned long long*)&v) : "memory");
        }
        asm volatile("barrier.cluster.arrive.aligned;" ::: "memory");
        #pragma unroll
        for (int r = 0; r < 4; r++)
            g_seq[((size_t)(b0 + r0 + r) * TT + t) * HID + gu] = hnew[r];
        asm volatile("barrier.cluster.wait.aligned;" ::: "memory");
    }
}

// ---- post: out = mish(seq) @ W_out + b_out (FFMA2 GEMV) --------------------
__global__ __launch_bounds__(256) void post_kernel(
    const float* __restrict__ W_out, const float* __restrict__ b_out,
    float* __restrict__ out)
{
    __shared__ float s_m2[HID][32];   // 32 KB, [k][row]

    const int tid = threadIdx.x;
    const size_t row0 = (size_t)blockIdx.x * 32;

    // stage A: mish, transposed store
    {
        const int row = tid & 31;
        const int kc  = (tid >> 5) * 32;
        const float* src = g_seq + (row0 + row) * HID + kc;
        #pragma unroll
        for (int c = 0; c < 8; c++) {
            float4 v = *(const float4*)(src + 4 * c);
            float hv[4] = {v.x, v.y, v.z, v.w};
            #pragma unroll
            for (int e = 0; e < 4; e++) {
                float h = hv[e];
                float sp = __logf(1.f + __expf(h));
                s_m2[kc + 4 * c + e][row] = h * tanha(sp);
            }
        }
    }
    __syncthreads();

    // stage B: GEMV
    if (tid < 192) {
        const int pg = tid / 24;
        const int l  = tid - pg * 24;
        float2 a0 = make_float2(0.f, 0.f), a1 = make_float2(0.f, 0.f);
        #pragma unroll 4
        for (int k = 0; k < HID; k++) {
            float4 m4 = *(const float4*)&s_m2[k][4 * pg];
            float w = __ldg(W_out + k * LAT + l);
            float2 w2 = make_float2(w, w);
            fma2(a0, w2, make_float2(m4.x, m4.y));
            fma2(a1, w2, make_float2(m4.z, m4.w));
        }
        const float bl = b_out[l];
        out[(row0 + 4 * pg + 0) * LAT + l] = a0.x + bl;
        out[(row0 + 4 * pg + 1) * LAT + l] = a0.y + bl;
        out[(row0 + 4 * pg + 2) * LAT + l] = a1.x + bl;
        out[(row0 + 4 * pg + 3) * LAT + l] = a1.y + bl;
    }
}

// ---------------------------------------------------------------------------
extern "C" void kernel_launch(void* const* d_in, const int* in_sizes, int n_in,
                              void* d_out, int out_size) {
    const float* obs     = (const float*)d_in[0];
    const int*   is_init = (const int*)  d_in[1];
    const float* hx      = (const float*)d_in[2];
    const float* W_in    = (const float*)d_in[3];
    const float* b_in    = (const float*)d_in[4];
    const float* W_ih    = (const float*)d_in[5];
    const float* b_ih    = (const float*)d_in[6];
    const float* W_hh    = (const float*)d_in[7];
    const float* b_hh    = (const float*)d_in[8];
    const float* W_out   = (const float*)d_in[9];
    const float* b_out   = (const float*)d_in[10];

    float* out     = (float*)d_out;                 // [B,T,LAT]
    float* h_final = out + (size_t)BB * TT * LAT;   // [B,HID]

    tr_kernel<<<((HID / 4) * G3 + 255) / 256, 256>>>(W_hh);
    pre_kernel<<<(BB * TT) / 32, 256>>>(obs, W_in, b_in, W_ih, b_ih);
    rec_kernel<<<BB / 8, 512>>>(is_init, hx, b_hh, h_final);
    post_kernel<<<(BB * TT) / 32, 256>>>(W_out, b_out, out);
}